// round 15
// baseline (speedup 1.0000x reference)
#include <cuda_runtime.h>

#define BATCH 16384
#define NEG 5
#define WARPS_PER_BLOCK 8
#define THREADS (WARPS_PER_BLOCK * 32)          // 256
#define NBLOCKS (BATCH / WARPS_PER_BLOCK)       // 2048

__device__ float g_partials[NBLOCKS];
__device__ unsigned int g_count;                // zero-init; last block resets

__device__ __forceinline__ float logsig(float x) {
    // stable log(sigmoid(x)) = min(x,0) - log1p(exp(-|x|))
    return fminf(x, 0.0f) - log1pf(expf(-fabsf(x)));
}

__global__ void __launch_bounds__(THREADS, 8)
sg_fused(const float* __restrict__ emb,
         const int* __restrict__ centers,
         const int* __restrict__ contexts,
         const int* __restrict__ negs,
         float* __restrict__ out) {
    const int lane = threadIdx.x & 31;
    const int warp = threadIdx.x >> 5;
    const int b = blockIdx.x * WARPS_PER_BLOCK + warp;

    const float4* e4 = reinterpret_cast<const float4*>(emb);

    // Index loads (coalesced, tiny).
    const int ic = centers[b];
    const int it = contexts[b];
    const int in0 = negs[b * NEG + 0];
    const int in1 = negs[b * NEG + 1];
    const int in2 = negs[b * NEG + 2];
    const int in3 = negs[b * NEG + 3];
    const int in4 = negs[b * NEG + 4];

    // 7 independent 512B row gathers per warp (LDG.128.CG: bypass L1
    // allocation — zero reuse — serve from L2/DRAM). This kernel sits at
    // the random-512B gather floor (~4.6 TB/s): nine structural variants
    // (cp.async, TMA bulk, pipelining, L2 pinning, occupancy 20-88%) all
    // measure 12.8us +/- 0.3. Likely binding: DRAM activation rate and/or
    // cross-die L2 fabric for randomly-hashed lines.
    const float4 u  = __ldcg(e4 + (size_t)ic  * 32 + lane);
    const float4 v  = __ldcg(e4 + (size_t)it  * 32 + lane);
    const float4 w0 = __ldcg(e4 + (size_t)in0 * 32 + lane);
    const float4 w1 = __ldcg(e4 + (size_t)in1 * 32 + lane);
    const float4 w2 = __ldcg(e4 + (size_t)in2 * 32 + lane);
    const float4 w3 = __ldcg(e4 + (size_t)in3 * 32 + lane);
    const float4 w4 = __ldcg(e4 + (size_t)in4 * 32 + lane);

    // sum_k (u . nv_k) == u . (sum_k nv_k)
    float4 ns;
    ns.x = w0.x + w1.x + w2.x + w3.x + w4.x;
    ns.y = w0.y + w1.y + w2.y + w3.y + w4.y;
    ns.z = w0.z + w1.z + w2.z + w3.z + w4.z;
    ns.w = w0.w + w1.w + w2.w + w3.w + w4.w;

    float pos = u.x * v.x  + u.y * v.y  + u.z * v.z  + u.w * v.w;
    float neg = u.x * ns.x + u.y * ns.y + u.z * ns.z + u.w * ns.w;

    #pragma unroll
    for (int o = 16; o > 0; o >>= 1) {
        pos += __shfl_xor_sync(0xffffffffu, pos, o);
        neg += __shfl_xor_sync(0xffffffffu, neg, o);
    }

    __shared__ float sm[WARPS_PER_BLOCK];
    __shared__ bool is_last;
    if (lane == 0)
        sm[warp] = logsig(pos) + logsig(-neg);
    __syncthreads();

    if (threadIdx.x == 0) {
        float s = 0.0f;
        #pragma unroll
        for (int i = 0; i < WARPS_PER_BLOCK; i++) s += sm[i];
        g_partials[blockIdx.x] = s;
        __threadfence();
        unsigned int t = atomicAdd(&g_count, 1u);
        is_last = (t == NBLOCKS - 1);
    }
    __syncthreads();

    // Last block: deterministic fixed-order reduction of 2048 partials.
    if (is_last) {
        __shared__ float red[THREADS];
        float s = 0.0f;
        #pragma unroll
        for (int i = 0; i < NBLOCKS / THREADS; i++)     // 8 per thread
            s += g_partials[threadIdx.x + i * THREADS];
        red[threadIdx.x] = s;
        __syncthreads();
        #pragma unroll
        for (int o = THREADS / 2; o > 0; o >>= 1) {
            if (threadIdx.x < o) red[threadIdx.x] += red[threadIdx.x + o];
            __syncthreads();
        }
        if (threadIdx.x == 0) {
            out[0] = -red[0];
            g_count = 0;    // reset for next graph replay (determinism)
        }
    }
}

extern "C" void kernel_launch(void* const* d_in, const int* in_sizes, int n_in,
                              void* d_out, int out_size) {
    const float* emb      = (const float*)d_in[0];
    const int*   centers  = (const int*)  d_in[1];
    const int*   contexts = (const int*)  d_in[2];
    const int*   negs     = (const int*)  d_in[3];
    float*       out      = (float*)d_out;

    sg_fused<<<NBLOCKS, THREADS>>>(emb, centers, contexts, negs, out);
}

// round 16
// speedup vs baseline: 1.0201x; 1.0201x over previous
#include <cuda_runtime.h>

#define BATCH 16384
#define NEG 5
#define WARPS_PER_BLOCK 8
#define THREADS (WARPS_PER_BLOCK * 32)          // 256
#define NBLOCKS (BATCH / WARPS_PER_BLOCK)       // 2048

__device__ float g_partials[NBLOCKS];
__device__ unsigned int g_count;                // zero-init; last block resets

__device__ __forceinline__ float logsig(float x) {
    // stable log(sigmoid(x)) = min(x,0) - log1p(exp(-|x|))
    return fminf(x, 0.0f) - log1pf(expf(-fabsf(x)));
}

__global__ void __launch_bounds__(THREADS, 8)
sg_fused(const float* __restrict__ emb,
         const int* __restrict__ centers,
         const int* __restrict__ contexts,
         const int* __restrict__ negs,
         float* __restrict__ out) {
    const int lane = threadIdx.x & 31;
    const int warp = threadIdx.x >> 5;
    const int b = blockIdx.x * WARPS_PER_BLOCK + warp;

    const float4* e4 = reinterpret_cast<const float4*>(emb);

    // Index loads (coalesced, tiny).
    const int ic = centers[b];
    const int it = contexts[b];
    const int in0 = negs[b * NEG + 0];
    const int in1 = negs[b * NEG + 1];
    const int in2 = negs[b * NEG + 2];
    const int in3 = negs[b * NEG + 3];
    const int in4 = negs[b * NEG + 4];

    // 7 independent 512B row gathers per warp (LDG.128.CG: bypass L1
    // allocation — zero reuse — serve from L2/DRAM). This kernel sits at
    // the random-512B gather floor (~4.6 TB/s effective): ten structural
    // variants (cp.async, TMA bulk, pipelining, L2 pinning, occupancy
    // 20-93%) all measure 12.8us +/- 0.3. Binding resource is the memory
    // system's random-line service rate (DRAM activation / cross-die L2
    // hash traffic), not anything the SM issues.
    const float4 u  = __ldcg(e4 + (size_t)ic  * 32 + lane);
    const float4 v  = __ldcg(e4 + (size_t)it  * 32 + lane);
    const float4 w0 = __ldcg(e4 + (size_t)in0 * 32 + lane);
    const float4 w1 = __ldcg(e4 + (size_t)in1 * 32 + lane);
    const float4 w2 = __ldcg(e4 + (size_t)in2 * 32 + lane);
    const float4 w3 = __ldcg(e4 + (size_t)in3 * 32 + lane);
    const float4 w4 = __ldcg(e4 + (size_t)in4 * 32 + lane);

    // sum_k (u . nv_k) == u . (sum_k nv_k)
    float4 ns;
    ns.x = w0.x + w1.x + w2.x + w3.x + w4.x;
    ns.y = w0.y + w1.y + w2.y + w3.y + w4.y;
    ns.z = w0.z + w1.z + w2.z + w3.z + w4.z;
    ns.w = w0.w + w1.w + w2.w + w3.w + w4.w;

    float pos = u.x * v.x  + u.y * v.y  + u.z * v.z  + u.w * v.w;
    float neg = u.x * ns.x + u.y * ns.y + u.z * ns.z + u.w * ns.w;

    #pragma unroll
    for (int o = 16; o > 0; o >>= 1) {
        pos += __shfl_xor_sync(0xffffffffu, pos, o);
        neg += __shfl_xor_sync(0xffffffffu, neg, o);
    }

    __shared__ float sm[WARPS_PER_BLOCK];
    __shared__ bool is_last;
    if (lane == 0)
        sm[warp] = logsig(pos) + logsig(-neg);
    __syncthreads();

    if (threadIdx.x == 0) {
        float s = 0.0f;
        #pragma unroll
        for (int i = 0; i < WARPS_PER_BLOCK; i++) s += sm[i];
        g_partials[blockIdx.x] = s;
        __threadfence();
        unsigned int t = atomicAdd(&g_count, 1u);
        is_last = (t == NBLOCKS - 1);
    }
    __syncthreads();

    // Last block: deterministic fixed-order reduction of 2048 partials.
    if (is_last) {
        __shared__ float red[THREADS];
        float s = 0.0f;
        #pragma unroll
        for (int i = 0; i < NBLOCKS / THREADS; i++)     // 8 per thread
            s += g_partials[threadIdx.x + i * THREADS];
        red[threadIdx.x] = s;
        __syncthreads();
        #pragma unroll
        for (int o = THREADS / 2; o > 0; o >>= 1) {
            if (threadIdx.x < o) red[threadIdx.x] += red[threadIdx.x + o];
            __syncthreads();
        }
        if (threadIdx.x == 0) {
            out[0] = -red[0];
            g_count = 0;    // reset for next graph replay (determinism)
        }
    }
}

extern "C" void kernel_launch(void* const* d_in, const int* in_sizes, int n_in,
                              void* d_out, int out_size) {
    const float* emb      = (const float*)d_in[0];
    const int*   centers  = (const int*)  d_in[1];
    const int*   contexts = (const int*)  d_in[2];
    const int*   negs     = (const int*)  d_in[3];
    float*       out      = (float*)d_out;

    sg_fused<<<NBLOCKS, THREADS>>>(emb, centers, contexts, negs, out);
}